// round 1
// baseline (speedup 1.0000x reference)
#include <cuda_runtime.h>
#include <math.h>

#define BB     4
#define NN     1024
#define DIMC   512
#define DEPTHL 4
#define HEADS  8
#define DH     64
#define TCDD   512
#define HIDD   512
#define INNERC 2048
#define MAXREL 32
#define SCALEQ 0.125f
#define LNEPS  1e-5f

// ---------------- scratch (device globals; no allocation allowed) -----------
__device__ float g_tact[BB * TCDD];
__device__ float g_scsh[BB * 2 * INNERC];
__device__ float g_xn[BB * NN * DIMC];
__device__ float g_q[BB * NN * HIDD];
__device__ float g_kv[BB * NN * 2 * HIDD];
__device__ float g_sim[(size_t)BB * HEADS * NN * NN];
__device__ float g_ao[BB * NN * HIDD];
__device__ float g_hb[BB * NN * INNERC];

// ---------------- small elementwise kernels ---------------------------------
__global__ void silu_time_k(const float* __restrict__ tm, float* __restrict__ out) {
    int i = blockIdx.x * 256 + threadIdx.x;
    if (i < BB * TCDD) {
        float v = tm[i];
        out[i] = v / (1.f + __expf(-v));
    }
}

__global__ void init_x_k(const float* __restrict__ xin, const float* __restrict__ mask,
                         float* __restrict__ x) {
    int i = blockIdx.x * 256 + threadIdx.x;
    if (i < BB * NN * DIMC) x[i] = xin[i] * mask[i / DIMC];
}

__global__ void modulate_k(float* __restrict__ h, const float* __restrict__ scsh) {
    int i = blockIdx.x * 256 + threadIdx.x;
    int c = i % INNERC;
    int b = i / (NN * INNERC);
    float sc = scsh[b * 2 * INNERC + c];
    float sh = scsh[b * 2 * INNERC + INNERC + c];
    h[i] = h[i] * (sc + 1.f) + sh;
}

// t_act[b] @ W[K, Ncols] + bias  -> out[b, Ncols]
__global__ void time_gemm_k(const float* __restrict__ tact, const float* __restrict__ W,
                            const float* __restrict__ bias, float* __restrict__ out,
                            int K, int Ncols) {
    int n = blockIdx.x * 256 + threadIdx.x;
    int b = blockIdx.y;
    if (n >= Ncols) return;
    const float* t = tact + b * K;
    float acc = bias[n];
    for (int k = 0; k < K; k++) acc += t[k] * W[(size_t)k * Ncols + n];
    out[(size_t)b * Ncols + n] = acc;
}

// LayerNorm (+ optional AdaLN modulation, + optional row mask). One block per row.
__global__ void ln_mod_k(const float* __restrict__ x, const float* __restrict__ g,
                         const float* __restrict__ scsh, const float* __restrict__ mask,
                         float* __restrict__ out, int useMod) {
    int row = blockIdx.x;
    int t = threadIdx.x;
    const float* xr = x + (size_t)row * DIMC;
    float v0 = xr[t], v1 = xr[t + 256];
    __shared__ float r1[256], r2[256];
    r1[t] = v0 + v1;
    r2[t] = v0 * v0 + v1 * v1;
    __syncthreads();
    for (int off = 128; off > 0; off >>= 1) {
        if (t < off) { r1[t] += r1[t + off]; r2[t] += r2[t + off]; }
        __syncthreads();
    }
    float m = r1[0] * (1.f / DIMC);
    float var = r2[0] * (1.f / DIMC) - m * m;
    float rstd = rsqrtf(var + LNEPS);
    int b = row / NN;
    float mk = mask ? mask[row] : 1.f;
    for (int c = t; c < DIMC; c += 256) {
        float val = (xr[c] - m) * rstd * g[c];
        if (useMod)
            val = val * (scsh[b * 2 * DIMC + c] + 1.f) + scsh[b * 2 * DIMC + DIMC + c];
        out[(size_t)row * DIMC + c] = val * mk;
    }
}

// ---------------- generic SGEMM: C[M,Ncols] = A[M,K] @ B[K,Ncols] ------------
// mode 0: C = acc*alpha (+bias)       (q / kv)
// mode 1: C = silu(acc + bias)        (ff_in)
// mode 2: C = residual + acc*rowmask  (to_out)
// mode 3: C = (residual + acc + bias)*rowmask  (ff_out)
__global__ __launch_bounds__(256)
void sgemm_k(const float* __restrict__ A, const float* __restrict__ Bm,
             float* __restrict__ C, int M, int Ncols, int K,
             const float* __restrict__ bias, const float* __restrict__ residual,
             const float* __restrict__ rowmask, float alpha, int mode) {
    __shared__ float As[8][128];
    __shared__ float Bs[8][128];
    int t = threadIdx.x;
    int tx = t % 16, ty = t / 16;
    int rowBase = blockIdx.y * 128, colBase = blockIdx.x * 128;
    int aRow = t >> 1, aCol4 = (t & 1) * 4;
    int bRow = t >> 5, bCol4 = (t & 31) * 4;
    float acc[8][8];
#pragma unroll
    for (int i = 0; i < 8; i++)
#pragma unroll
        for (int j = 0; j < 8; j++) acc[i][j] = 0.f;

    for (int k0 = 0; k0 < K; k0 += 8) {
        float4 av = *(const float4*)(A + (size_t)(rowBase + aRow) * K + k0 + aCol4);
        As[aCol4 + 0][aRow] = av.x;
        As[aCol4 + 1][aRow] = av.y;
        As[aCol4 + 2][aRow] = av.z;
        As[aCol4 + 3][aRow] = av.w;
        *(float4*)&Bs[bRow][bCol4] =
            *(const float4*)(Bm + (size_t)(k0 + bRow) * Ncols + colBase + bCol4);
        __syncthreads();
#pragma unroll
        for (int k = 0; k < 8; k++) {
            float ra[8], rb[8];
            *(float4*)(ra)     = *(float4*)&As[k][ty * 8];
            *(float4*)(ra + 4) = *(float4*)&As[k][ty * 8 + 4];
            *(float4*)(rb)     = *(float4*)&Bs[k][tx * 8];
            *(float4*)(rb + 4) = *(float4*)&Bs[k][tx * 8 + 4];
#pragma unroll
            for (int i = 0; i < 8; i++)
#pragma unroll
                for (int j = 0; j < 8; j++) acc[i][j] += ra[i] * rb[j];
        }
        __syncthreads();
    }

#pragma unroll
    for (int i = 0; i < 8; i++) {
        int r = rowBase + ty * 8 + i;
        float rm = (mode >= 2) ? rowmask[r] : 1.f;
#pragma unroll
        for (int j = 0; j < 8; j++) {
            int c = colBase + tx * 8 + j;
            size_t off = (size_t)r * Ncols + c;
            float v = acc[i][j] * alpha;
            if (mode == 0) {
                if (bias) v += bias[c];
            } else if (mode == 1) {
                v += bias[c];
                v = v / (1.f + __expf(-v));
            } else if (mode == 2) {
                v = residual[off] + v * rm;
            } else {
                v = (residual[off] + v + bias[c]) * rm;
            }
            C[off] = v;
        }
    }
}

// ---------------- attention kernels ------------------------------------------
// sim[b,h,i,j] = sum_d q[b,i,h,d]*k[b,j,h,d] + relpos_bias - (1-m_i*m_j)*1e6
__global__ __launch_bounds__(256)
void qk_k(const float* __restrict__ q, const float* __restrict__ kv,
          const int* __restrict__ ri, const float* __restrict__ mask,
          const float* __restrict__ rw, const float* __restrict__ rb,
          float* __restrict__ sim) {
    int bz = blockIdx.z;
    int b = bz / HEADS, h = bz % HEADS;
    int i0 = blockIdx.y * 128, j0 = blockIdx.x * 128;
    __shared__ float Qs[32][128];
    __shared__ float Ks[32][128];
    int t = threadIdx.x;
    int tx = t % 16, ty = t / 16;
    float acc[8][8];
#pragma unroll
    for (int i = 0; i < 8; i++)
#pragma unroll
        for (int j = 0; j < 8; j++) acc[i][j] = 0.f;

    const float* qb = q + (size_t)b * NN * HIDD + h * DH;
    for (int k0 = 0; k0 < DH; k0 += 32) {
#pragma unroll
        for (int l = 0; l < 4; l++) {
            int idx = t + 256 * l;
            int r = idx >> 3, dg = (idx & 7) * 4;
            float4 v = *(const float4*)(qb + (size_t)(i0 + r) * HIDD + k0 + dg);
            Qs[dg + 0][r] = v.x; Qs[dg + 1][r] = v.y;
            Qs[dg + 2][r] = v.z; Qs[dg + 3][r] = v.w;
            const float* kp = kv + ((size_t)(b * NN + j0 + r) * 2) * HIDD + h * DH + k0 + dg;
            float4 w = *(const float4*)kp;
            Ks[dg + 0][r] = w.x; Ks[dg + 1][r] = w.y;
            Ks[dg + 2][r] = w.z; Ks[dg + 3][r] = w.w;
        }
        __syncthreads();
#pragma unroll
        for (int k = 0; k < 32; k++) {
            float ra[8], rk[8];
            *(float4*)(ra)     = *(float4*)&Qs[k][ty * 8];
            *(float4*)(ra + 4) = *(float4*)&Qs[k][ty * 8 + 4];
            *(float4*)(rk)     = *(float4*)&Ks[k][tx * 8];
            *(float4*)(rk + 4) = *(float4*)&Ks[k][tx * 8 + 4];
#pragma unroll
            for (int i = 0; i < 8; i++)
#pragma unroll
                for (int j = 0; j < 8; j++) acc[i][j] += ra[i] * rk[j];
        }
        __syncthreads();
    }

    int rii[8];
    float mi[8];
#pragma unroll
    for (int ii = 0; ii < 8; ii++) {
        int i = i0 + ty * 8 + ii;
        rii[ii] = ri[b * NN + i];
        mi[ii] = mask[b * NN + i];
    }
    float rbh = rb[h];
#pragma unroll
    for (int jj = 0; jj < 8; jj++) {
        int j = j0 + tx * 8 + jj;
        int rj = ri[b * NN + j];
        float mj = mask[b * NN + j];
#pragma unroll
        for (int ii = 0; ii < 8; ii++) {
            int d = rii[ii] - rj;
            d = (d < -MAXREL) ? -MAXREL : (d > MAXREL ? MAXREL : d);
            d += MAXREL;
            float bias = rw[d * HEADS + h] + rbh;
            float val = acc[ii][jj] + bias - (1.f - mi[ii] * mj) * 1e6f;
            sim[((size_t)(b * HEADS + h) * NN + (i0 + ty * 8 + ii)) * NN + j] = val;
        }
    }
}

__global__ void softmax_k(float* __restrict__ sim) {
    size_t row = blockIdx.x;
    float* p = sim + row * (size_t)NN;
    int t = threadIdx.x;
    float vals[4];
    float mx = -1e30f;
#pragma unroll
    for (int i = 0; i < 4; i++) {
        vals[i] = p[t + 256 * i];
        mx = fmaxf(mx, vals[i]);
    }
    __shared__ float red[256];
    red[t] = mx;
    __syncthreads();
    for (int off = 128; off > 0; off >>= 1) {
        if (t < off) red[t] = fmaxf(red[t], red[t + off]);
        __syncthreads();
    }
    mx = red[0];
    __syncthreads();
    float sum = 0.f;
#pragma unroll
    for (int i = 0; i < 4; i++) {
        vals[i] = __expf(vals[i] - mx);
        sum += vals[i];
    }
    red[t] = sum;
    __syncthreads();
    for (int off = 128; off > 0; off >>= 1) {
        if (t < off) red[t] += red[t + off];
        __syncthreads();
    }
    float inv = 1.f / red[0];
#pragma unroll
    for (int i = 0; i < 4; i++) p[t + 256 * i] = vals[i] * inv;
}

// ao[b,i,h,d] = sum_j attn[b,h,i,j] * v[b,j,h,d]
__global__ __launch_bounds__(256)
void av_k(const float* __restrict__ sim, const float* __restrict__ kv,
          float* __restrict__ ao) {
    int bz = blockIdx.y;
    int b = bz / HEADS, h = bz % HEADS;
    int i0 = blockIdx.x * 128;
    __shared__ float As[16][128];
    __shared__ float Vs[16][64];
    int t = threadIdx.x;
    int tx = t % 16, ty = t / 16;
    float acc[8][4];
#pragma unroll
    for (int i = 0; i < 8; i++)
#pragma unroll
        for (int j = 0; j < 4; j++) acc[i][j] = 0.f;

    const float* ap = sim + (size_t)(b * HEADS + h) * NN * NN;
    for (int j0 = 0; j0 < NN; j0 += 16) {
#pragma unroll
        for (int l = 0; l < 2; l++) {
            int idx = t + 256 * l;
            int r = idx >> 2, jg = (idx & 3) * 4;
            float4 v = *(const float4*)(ap + (size_t)(i0 + r) * NN + j0 + jg);
            As[jg + 0][r] = v.x; As[jg + 1][r] = v.y;
            As[jg + 2][r] = v.z; As[jg + 3][r] = v.w;
        }
        {
            int j = t / 16, dg = (t % 16) * 4;
            float4 v = *(const float4*)(kv + ((size_t)(b * NN + j0 + j) * 2 + 1) * HIDD +
                                        h * DH + dg);
            *(float4*)&Vs[j][dg] = v;
        }
        __syncthreads();
#pragma unroll
        for (int k = 0; k < 16; k++) {
            float ra[8], rv[4];
            *(float4*)(ra)     = *(float4*)&As[k][ty * 8];
            *(float4*)(ra + 4) = *(float4*)&As[k][ty * 8 + 4];
            *(float4*)(rv)     = *(float4*)&Vs[k][tx * 4];
#pragma unroll
            for (int i = 0; i < 8; i++)
#pragma unroll
                for (int j = 0; j < 4; j++) acc[i][j] += ra[i] * rv[j];
        }
        __syncthreads();
    }
#pragma unroll
    for (int i = 0; i < 8; i++)
#pragma unroll
        for (int j = 0; j < 4; j++)
            ao[((size_t)b * NN + i0 + ty * 8 + i) * HIDD + h * DH + tx * 4 + j] = acc[i][j];
}

// ---------------- launch -----------------------------------------------------
extern "C" void kernel_launch(void* const* d_in, const int* in_sizes, int n_in,
                              void* d_out, int out_size) {
    const float* x_in      = (const float*)d_in[0];
    const float* time_in   = (const float*)d_in[1];
    const float* seq_mask  = (const float*)d_in[2];
    const int*   res_idx   = (const int*)d_in[3];
    const float* relpos_w  = (const float*)d_in[4];
    const float* relpos_b  = (const float*)d_in[5];
    const float* attn_g    = (const float*)d_in[6];
    const float* attn_tw   = (const float*)d_in[7];
    const float* attn_tb   = (const float*)d_in[8];
    const float* to_q_w    = (const float*)d_in[9];
    const float* to_kv_w   = (const float*)d_in[10];
    const float* to_out_w  = (const float*)d_in[11];
    const float* ff_g      = (const float*)d_in[12];
    const float* ff_tw     = (const float*)d_in[13];
    const float* ff_tb     = (const float*)d_in[14];
    const float* ff_in_w   = (const float*)d_in[15];
    const float* ff_in_b   = (const float*)d_in[16];
    const float* ff_out_w  = (const float*)d_in[17];
    const float* ff_out_b  = (const float*)d_in[18];

    float *tact, *scsh, *xn, *q, *kv, *sim, *ao, *hb;
    cudaGetSymbolAddress((void**)&tact, g_tact);
    cudaGetSymbolAddress((void**)&scsh, g_scsh);
    cudaGetSymbolAddress((void**)&xn, g_xn);
    cudaGetSymbolAddress((void**)&q, g_q);
    cudaGetSymbolAddress((void**)&kv, g_kv);
    cudaGetSymbolAddress((void**)&sim, g_sim);
    cudaGetSymbolAddress((void**)&ao, g_ao);
    cudaGetSymbolAddress((void**)&hb, g_hb);

    float* x = (float*)d_out;
    const int M = BB * NN;

    init_x_k<<<(BB * NN * DIMC + 255) / 256, 256>>>(x_in, seq_mask, x);
    silu_time_k<<<(BB * TCDD + 255) / 256, 256>>>(time_in, tact);

    for (int d = 0; d < DEPTHL; d++) {
        // --- attention block ---
        time_gemm_k<<<dim3((2 * DIMC + 255) / 256, BB), 256>>>(
            tact, attn_tw + (size_t)d * TCDD * 2 * DIMC, attn_tb + (size_t)d * 2 * DIMC,
            scsh, TCDD, 2 * DIMC);
        ln_mod_k<<<M, 256>>>(x, attn_g + d * DIMC, scsh, seq_mask, xn, 1);
        sgemm_k<<<dim3(HIDD / 128, M / 128), 256>>>(
            xn, to_q_w + (size_t)d * DIMC * HIDD, q, M, HIDD, DIMC,
            nullptr, nullptr, nullptr, SCALEQ, 0);
        sgemm_k<<<dim3(2 * HIDD / 128, M / 128), 256>>>(
            x, to_kv_w + (size_t)d * DIMC * 2 * HIDD, kv, M, 2 * HIDD, DIMC,
            nullptr, nullptr, nullptr, 1.f, 0);
        qk_k<<<dim3(NN / 128, NN / 128, BB * HEADS), 256>>>(
            q, kv, res_idx, seq_mask, relpos_w, relpos_b, sim);
        softmax_k<<<BB * HEADS * NN, 256>>>(sim);
        av_k<<<dim3(NN / 128, BB * HEADS), 256>>>(sim, kv, ao);
        sgemm_k<<<dim3(DIMC / 128, M / 128), 256>>>(
            ao, to_out_w + (size_t)d * HIDD * DIMC, x, M, DIMC, HIDD,
            nullptr, x, seq_mask, 1.f, 2);

        // --- feed-forward block ---
        time_gemm_k<<<dim3((2 * INNERC + 255) / 256, BB), 256>>>(
            tact, ff_tw + (size_t)d * TCDD * 2 * INNERC, ff_tb + (size_t)d * 2 * INNERC,
            scsh, TCDD, 2 * INNERC);
        ln_mod_k<<<M, 256>>>(x, ff_g + d * DIMC, nullptr, nullptr, xn, 0);
        sgemm_k<<<dim3(INNERC / 128, M / 128), 256>>>(
            xn, ff_in_w + (size_t)d * DIMC * INNERC, hb, M, INNERC, DIMC,
            ff_in_b + (size_t)d * INNERC, nullptr, nullptr, 1.f, 1);
        modulate_k<<<(BB * NN * INNERC) / 256, 256>>>(hb, scsh);
        sgemm_k<<<dim3(DIMC / 128, M / 128), 256>>>(
            hb, ff_out_w + (size_t)d * INNERC * DIMC, x, M, DIMC, INNERC,
            ff_out_b + (size_t)d * DIMC, x, seq_mask, 1.f, 3);
    }
}

// round 2
// speedup vs baseline: 2.2556x; 2.2556x over previous
#include <cuda_runtime.h>
#include <math.h>
#include <stdint.h>

#define BB     4
#define NN     1024
#define DIMC   512
#define DEPTHL 4
#define HEADS  8
#define DH     64
#define TCDD   512
#define HIDD   512
#define INNERC 2048
#define MAXREL 32
#define SCALEQ 0.125f
#define LNEPS  1e-5f

// ---------------- scratch (device globals; no allocation allowed) -----------
__device__ float g_tact[BB * TCDD];
__device__ float g_scsh[BB * 2 * INNERC];
__device__ float g_xn[BB * NN * DIMC];
__device__ float g_q[BB * NN * HIDD];
__device__ float g_kv[BB * NN * 2 * HIDD];
__device__ float g_sim[(size_t)BB * HEADS * NN * NN];
__device__ float g_ao[BB * NN * HIDD];
__device__ float g_hb[BB * NN * INNERC];

// ---------------- helpers ----------------------------------------------------
__device__ __forceinline__ float tf32r(float x) {
    uint32_t u;
    asm("cvt.rna.tf32.f32 %0, %1;" : "=r"(u) : "f"(x));
    return __uint_as_float(u);
}

#define MMA_TF32(c, a0, a1, a2, a3, b0, b1)                                     \
    asm volatile(                                                               \
        "mma.sync.aligned.m16n8k8.row.col.f32.tf32.tf32.f32 "                   \
        "{%0,%1,%2,%3},{%4,%5,%6,%7},{%8,%9},{%0,%1,%2,%3};"                    \
        : "+f"(c[0]), "+f"(c[1]), "+f"(c[2]), "+f"(c[3])                        \
        : "r"(a0), "r"(a1), "r"(a2), "r"(a3), "r"(b0), "r"(b1))

// ---------------- small elementwise kernels ---------------------------------
__global__ void silu_time_k(const float* __restrict__ tm, float* __restrict__ out) {
    int i = blockIdx.x * 256 + threadIdx.x;
    if (i < BB * TCDD) {
        float v = tm[i];
        out[i] = v / (1.f + __expf(-v));
    }
}

__global__ void init_x_k(const float* __restrict__ xin, const float* __restrict__ mask,
                         float* __restrict__ x) {
    int i = blockIdx.x * 256 + threadIdx.x;
    if (i < BB * NN * DIMC) x[i] = xin[i] * mask[i / DIMC];
}

// t_act[b] @ W[K, Ncols] + bias  -> out[b, Ncols]
__global__ void time_gemm_k(const float* __restrict__ tact, const float* __restrict__ W,
                            const float* __restrict__ bias, float* __restrict__ out,
                            int K, int Ncols) {
    int n = blockIdx.x * 256 + threadIdx.x;
    int b = blockIdx.y;
    if (n >= Ncols) return;
    const float* t = tact + b * K;
    float acc = bias[n];
    for (int k = 0; k < K; k++) acc += t[k] * W[(size_t)k * Ncols + n];
    out[(size_t)b * Ncols + n] = acc;
}

// LayerNorm (+ optional AdaLN modulation, + optional row mask). One block per row.
__global__ void ln_mod_k(const float* __restrict__ x, const float* __restrict__ g,
                         const float* __restrict__ scsh, const float* __restrict__ mask,
                         float* __restrict__ out, int useMod) {
    int row = blockIdx.x;
    int t = threadIdx.x;
    const float* xr = x + (size_t)row * DIMC;
    float v0 = xr[t], v1 = xr[t + 256];
    __shared__ float r1[256], r2[256];
    r1[t] = v0 + v1;
    r2[t] = v0 * v0 + v1 * v1;
    __syncthreads();
    for (int off = 128; off > 0; off >>= 1) {
        if (t < off) { r1[t] += r1[t + off]; r2[t] += r2[t + off]; }
        __syncthreads();
    }
    float m = r1[0] * (1.f / DIMC);
    float var = r2[0] * (1.f / DIMC) - m * m;
    float rstd = rsqrtf(var + LNEPS);
    int b = row / NN;
    float mk = mask ? mask[row] : 1.f;
    for (int c = t; c < DIMC; c += 256) {
        float val = (xr[c] - m) * rstd * g[c];
        if (useMod)
            val = val * (scsh[b * 2 * DIMC + c] + 1.f) + scsh[b * 2 * DIMC + DIMC + c];
        out[(size_t)row * DIMC + c] = val * mk;
    }
}

// ---------------- tf32 tensor-core GEMM: C[M,N] = A[M,K] @ B[K,N] ------------
// mode 0: C = acc*alpha (+bias)
// mode 1: C = silu(acc + bias) * (mod_sc+1) + mod_sh        (ff_in fused modulate)
// mode 2: C = residual + acc*rowmask                        (to_out)
// mode 3: C = (residual + acc + bias)*rowmask               (ff_out)
__global__ __launch_bounds__(256, 2)
void tgemm_k(const float* __restrict__ A, const float* __restrict__ Bm,
             float* __restrict__ C, int M, int Ncols, int K,
             const float* __restrict__ bias, const float* __restrict__ residual,
             const float* __restrict__ rowmask, const float* __restrict__ mod,
             float alpha, int mode) {
    __shared__ float As[16 * 136];  // [k][m], stride 136 (conflict-free frags)
    __shared__ float Bs[16 * 136];  // [k][n], stride 136
    int t = threadIdx.x;
    int lane = t & 31, warp = t >> 5;
    int gid = lane >> 2, tig = lane & 3;
    int wr = warp >> 1, wc = warp & 1;           // 4x2 warps, warp tile 32x64
    int rowBase = blockIdx.y * 128, colBase = blockIdx.x * 128;

    float acc[2][8][4];
#pragma unroll
    for (int i = 0; i < 2; i++)
#pragma unroll
        for (int j = 0; j < 8; j++)
#pragma unroll
            for (int c = 0; c < 4; c++) acc[i][j][c] = 0.f;

    for (int k0 = 0; k0 < K; k0 += 16) {
#pragma unroll
        for (int l = 0; l < 2; l++) {  // A tile 128x16
            int idx = t + 256 * l;
            int m = idx >> 2, kvi = idx & 3;
            float4 v = *(const float4*)(A + (size_t)(rowBase + m) * K + k0 + kvi * 4);
            As[(kvi * 4 + 0) * 136 + m] = tf32r(v.x);
            As[(kvi * 4 + 1) * 136 + m] = tf32r(v.y);
            As[(kvi * 4 + 2) * 136 + m] = tf32r(v.z);
            As[(kvi * 4 + 3) * 136 + m] = tf32r(v.w);
        }
#pragma unroll
        for (int l = 0; l < 2; l++) {  // B tile 16x128
            int idx = t + 256 * l;
            int kk = idx >> 5, nv = idx & 31;
            float4 v = *(const float4*)(Bm + (size_t)(k0 + kk) * Ncols + colBase + nv * 4);
            float4 cv = make_float4(tf32r(v.x), tf32r(v.y), tf32r(v.z), tf32r(v.w));
            *(float4*)&Bs[kk * 136 + nv * 4] = cv;
        }
        __syncthreads();
#pragma unroll
        for (int ks = 0; ks < 16; ks += 8) {
            uint32_t a[2][4];
#pragma unroll
            for (int mt = 0; mt < 2; mt++) {
                int m0 = wr * 32 + mt * 16;
                a[mt][0] = __float_as_uint(As[(ks + tig) * 136 + m0 + gid]);
                a[mt][1] = __float_as_uint(As[(ks + tig) * 136 + m0 + gid + 8]);
                a[mt][2] = __float_as_uint(As[(ks + tig + 4) * 136 + m0 + gid]);
                a[mt][3] = __float_as_uint(As[(ks + tig + 4) * 136 + m0 + gid + 8]);
            }
            uint32_t b[8][2];
#pragma unroll
            for (int nt = 0; nt < 8; nt++) {
                int n0 = wc * 64 + nt * 8;
                b[nt][0] = __float_as_uint(Bs[(ks + tig) * 136 + n0 + gid]);
                b[nt][1] = __float_as_uint(Bs[(ks + tig + 4) * 136 + n0 + gid]);
            }
#pragma unroll
            for (int mt = 0; mt < 2; mt++)
#pragma unroll
                for (int nt = 0; nt < 8; nt++)
                    MMA_TF32(acc[mt][nt], a[mt][0], a[mt][1], a[mt][2], a[mt][3],
                             b[nt][0], b[nt][1]);
        }
        __syncthreads();
    }

    // epilogue: c0/c1 at (gid, 2tig/2tig+1), c2/c3 at (gid+8, ...)
#pragma unroll
    for (int mt = 0; mt < 2; mt++)
#pragma unroll
        for (int half = 0; half < 2; half++) {
            int i = rowBase + wr * 32 + mt * 16 + gid + half * 8;
            int b = i / NN;
            float rm = (mode >= 2) ? rowmask[i] : 1.f;
#pragma unroll
            for (int nt = 0; nt < 8; nt++) {
                int j = colBase + wc * 64 + nt * 8 + tig * 2;
                size_t off = (size_t)i * Ncols + j;
                float v0 = acc[mt][nt][half * 2 + 0] * alpha;
                float v1 = acc[mt][nt][half * 2 + 1] * alpha;
                if (mode == 0) {
                    if (bias) { v0 += bias[j]; v1 += bias[j + 1]; }
                } else if (mode == 1) {
                    v0 += bias[j];
                    v1 += bias[j + 1];
                    v0 = v0 / (1.f + __expf(-v0));
                    v1 = v1 / (1.f + __expf(-v1));
                    float sc0 = mod[b * 2 * Ncols + j], sc1 = mod[b * 2 * Ncols + j + 1];
                    float sh0 = mod[b * 2 * Ncols + Ncols + j];
                    float sh1 = mod[b * 2 * Ncols + Ncols + j + 1];
                    v0 = v0 * (sc0 + 1.f) + sh0;
                    v1 = v1 * (sc1 + 1.f) + sh1;
                } else if (mode == 2) {
                    float2 r = *(const float2*)(residual + off);
                    v0 = r.x + v0 * rm;
                    v1 = r.y + v1 * rm;
                } else {
                    float2 r = *(const float2*)(residual + off);
                    v0 = (r.x + v0 + bias[j]) * rm;
                    v1 = (r.y + v1 + bias[j + 1]) * rm;
                }
                *(float2*)(C + off) = make_float2(v0, v1);
            }
        }
}

// ---------------- attention: QK^T (tf32 mma) ---------------------------------
__global__ __launch_bounds__(256, 2)
void qk_mma_k(const float* __restrict__ q, const float* __restrict__ kv,
              const int* __restrict__ ri, const float* __restrict__ mask,
              const float* __restrict__ rw, const float* __restrict__ rb,
              float* __restrict__ sim) {
    __shared__ float Qs[128 * 36];  // [i][d], stride 36
    __shared__ float Ks[128 * 36];  // [j][d], stride 36
    int bz = blockIdx.z;
    int b = bz / HEADS, h = bz % HEADS;
    int i0 = blockIdx.y * 128, j0 = blockIdx.x * 128;
    int t = threadIdx.x;
    int lane = t & 31, warp = t >> 5;
    int gid = lane >> 2, tig = lane & 3;
    int wr = warp >> 1, wc = warp & 1;

    float acc[2][8][4];
#pragma unroll
    for (int i = 0; i < 2; i++)
#pragma unroll
        for (int j = 0; j < 8; j++)
#pragma unroll
            for (int c = 0; c < 4; c++) acc[i][j][c] = 0.f;

#pragma unroll
    for (int k0 = 0; k0 < DH; k0 += 32) {
#pragma unroll
        for (int l = 0; l < 4; l++) {  // 128 rows x 32 d, for Q and K each
            int idx = t + 256 * l;
            int r = idx >> 3, dv = idx & 7;
            float4 v = *(const float4*)(q + (size_t)(b * NN + i0 + r) * HIDD + h * DH +
                                        k0 + dv * 4);
            *(float4*)&Qs[r * 36 + dv * 4] =
                make_float4(tf32r(v.x), tf32r(v.y), tf32r(v.z), tf32r(v.w));
            float4 w = *(const float4*)(kv + ((size_t)(b * NN + j0 + r) * 2) * HIDD +
                                        h * DH + k0 + dv * 4);
            *(float4*)&Ks[r * 36 + dv * 4] =
                make_float4(tf32r(w.x), tf32r(w.y), tf32r(w.z), tf32r(w.w));
        }
        __syncthreads();
#pragma unroll
        for (int ks = 0; ks < 32; ks += 8) {
            uint32_t a[2][4];
#pragma unroll
            for (int mt = 0; mt < 2; mt++) {
                int m0 = wr * 32 + mt * 16;
                a[mt][0] = __float_as_uint(Qs[(m0 + gid) * 36 + ks + tig]);
                a[mt][1] = __float_as_uint(Qs[(m0 + gid + 8) * 36 + ks + tig]);
                a[mt][2] = __float_as_uint(Qs[(m0 + gid) * 36 + ks + tig + 4]);
                a[mt][3] = __float_as_uint(Qs[(m0 + gid + 8) * 36 + ks + tig + 4]);
            }
            uint32_t bfr[8][2];
#pragma unroll
            for (int nt = 0; nt < 8; nt++) {
                int n0 = wc * 64 + nt * 8;
                bfr[nt][0] = __float_as_uint(Ks[(n0 + gid) * 36 + ks + tig]);
                bfr[nt][1] = __float_as_uint(Ks[(n0 + gid) * 36 + ks + tig + 4]);
            }
#pragma unroll
            for (int mt = 0; mt < 2; mt++)
#pragma unroll
                for (int nt = 0; nt < 8; nt++)
                    MMA_TF32(acc[mt][nt], a[mt][0], a[mt][1], a[mt][2], a[mt][3],
                             bfr[nt][0], bfr[nt][1]);
        }
        __syncthreads();
    }

    float rbh = rb[h];
#pragma unroll
    for (int mt = 0; mt < 2; mt++)
#pragma unroll
        for (int half = 0; half < 2; half++) {
            int i = i0 + wr * 32 + mt * 16 + gid + half * 8;
            int rii = ri[b * NN + i];
            float mi = mask[b * NN + i];
#pragma unroll
            for (int nt = 0; nt < 8; nt++) {
                int j = j0 + wc * 64 + nt * 8 + tig * 2;
                float v0 = acc[mt][nt][half * 2 + 0];
                float v1 = acc[mt][nt][half * 2 + 1];
                int d0 = rii - ri[b * NN + j];
                int d1 = rii - ri[b * NN + j + 1];
                d0 = min(max(d0, -MAXREL), MAXREL) + MAXREL;
                d1 = min(max(d1, -MAXREL), MAXREL) + MAXREL;
                float mj0 = mask[b * NN + j], mj1 = mask[b * NN + j + 1];
                v0 += rw[d0 * HEADS + h] + rbh - (1.f - mi * mj0) * 1e6f;
                v1 += rw[d1 * HEADS + h] + rbh - (1.f - mi * mj1) * 1e6f;
                *(float2*)(sim + ((size_t)(b * HEADS + h) * NN + i) * NN + j) =
                    make_float2(v0, v1);
            }
        }
}

__global__ void softmax_k(float* __restrict__ sim) {
    size_t row = blockIdx.x;
    float* p = sim + row * (size_t)NN;
    int t = threadIdx.x;
    float vals[4];
    float mx = -1e30f;
#pragma unroll
    for (int i = 0; i < 4; i++) {
        vals[i] = p[t + 256 * i];
        mx = fmaxf(mx, vals[i]);
    }
    __shared__ float red[256];
    red[t] = mx;
    __syncthreads();
    for (int off = 128; off > 0; off >>= 1) {
        if (t < off) red[t] = fmaxf(red[t], red[t + off]);
        __syncthreads();
    }
    mx = red[0];
    __syncthreads();
    float sum = 0.f;
#pragma unroll
    for (int i = 0; i < 4; i++) {
        vals[i] = __expf(vals[i] - mx);
        sum += vals[i];
    }
    red[t] = sum;
    __syncthreads();
    for (int off = 128; off > 0; off >>= 1) {
        if (t < off) red[t] += red[t + off];
        __syncthreads();
    }
    float inv = 1.f / red[0];
#pragma unroll
    for (int i = 0; i < 4; i++) p[t + 256 * i] = vals[i] * inv;
}

// ---------------- attention: A @ V (tf32 mma) --------------------------------
__global__ __launch_bounds__(256, 2)
void av_mma_k(const float* __restrict__ sim, const float* __restrict__ kv,
              float* __restrict__ ao) {
    __shared__ float As_[128 * 36];  // [i][j], stride 36
    __shared__ float Vs[32 * 68];    // [j][d], stride 68
    int bz = blockIdx.y;
    int b = bz / HEADS, h = bz % HEADS;
    int i0 = blockIdx.x * 128;
    int t = threadIdx.x;
    int lane = t & 31, warp = t >> 5;
    int gid = lane >> 2, tig = lane & 3;
    int wr = warp >> 1, wc = warp & 1;  // warp tile 32x32

    float acc[2][4][4];
#pragma unroll
    for (int i = 0; i < 2; i++)
#pragma unroll
        for (int j = 0; j < 4; j++)
#pragma unroll
            for (int c = 0; c < 4; c++) acc[i][j][c] = 0.f;

    const float* ap = sim + (size_t)(b * HEADS + h) * NN * NN;
    for (int j0 = 0; j0 < NN; j0 += 32) {
#pragma unroll
        for (int l = 0; l < 4; l++) {  // attn chunk 128x32
            int idx = t + 256 * l;
            int r = idx >> 3, jv = idx & 7;
            float4 v = *(const float4*)(ap + (size_t)(i0 + r) * NN + j0 + jv * 4);
            *(float4*)&As_[r * 36 + jv * 4] =
                make_float4(tf32r(v.x), tf32r(v.y), tf32r(v.z), tf32r(v.w));
        }
#pragma unroll
        for (int l = 0; l < 2; l++) {  // V chunk 32x64
            int idx = t + 256 * l;
            int r = idx >> 4, dv = idx & 15;
            float4 v = *(const float4*)(kv + ((size_t)(b * NN + j0 + r) * 2 + 1) * HIDD +
                                        h * DH + dv * 4);
            *(float4*)&Vs[r * 68 + dv * 4] =
                make_float4(tf32r(v.x), tf32r(v.y), tf32r(v.z), tf32r(v.w));
        }
        __syncthreads();
#pragma unroll
        for (int ks = 0; ks < 32; ks += 8) {
            uint32_t a[2][4];
#pragma unroll
            for (int mt = 0; mt < 2; mt++) {
                int m0 = wr * 32 + mt * 16;
                a[mt][0] = __float_as_uint(As_[(m0 + gid) * 36 + ks + tig]);
                a[mt][1] = __float_as_uint(As_[(m0 + gid + 8) * 36 + ks + tig]);
                a[mt][2] = __float_as_uint(As_[(m0 + gid) * 36 + ks + tig + 4]);
                a[mt][3] = __float_as_uint(As_[(m0 + gid + 8) * 36 + ks + tig + 4]);
            }
            uint32_t bfr[4][2];
#pragma unroll
            for (int nt = 0; nt < 4; nt++) {
                int n0 = wc * 32 + nt * 8;
                bfr[nt][0] = __float_as_uint(Vs[(ks + tig) * 68 + n0 + gid]);
                bfr[nt][1] = __float_as_uint(Vs[(ks + tig + 4) * 68 + n0 + gid]);
            }
#pragma unroll
            for (int mt = 0; mt < 2; mt++)
#pragma unroll
                for (int nt = 0; nt < 4; nt++)
                    MMA_TF32(acc[mt][nt], a[mt][0], a[mt][1], a[mt][2], a[mt][3],
                             bfr[nt][0], bfr[nt][1]);
        }
        __syncthreads();
    }

#pragma unroll
    for (int mt = 0; mt < 2; mt++)
#pragma unroll
        for (int half = 0; half < 2; half++) {
            int i = i0 + wr * 32 + mt * 16 + gid + half * 8;
#pragma unroll
            for (int nt = 0; nt < 4; nt++) {
                int dd = wc * 32 + nt * 8 + tig * 2;
                *(float2*)(ao + (size_t)(b * NN + i) * HIDD + h * DH + dd) =
                    make_float2(acc[mt][nt][half * 2 + 0], acc[mt][nt][half * 2 + 1]);
            }
        }
}

// ---------------- launch -----------------------------------------------------
extern "C" void kernel_launch(void* const* d_in, const int* in_sizes, int n_in,
                              void* d_out, int out_size) {
    const float* x_in      = (const float*)d_in[0];
    const float* time_in   = (const float*)d_in[1];
    const float* seq_mask  = (const float*)d_in[2];
    const int*   res_idx   = (const int*)d_in[3];
    const float* relpos_w  = (const float*)d_in[4];
    const float* relpos_b  = (const float*)d_in[5];
    const float* attn_g    = (const float*)d_in[6];
    const float* attn_tw   = (const float*)d_in[7];
    const float* attn_tb   = (const float*)d_in[8];
    const float* to_q_w    = (const float*)d_in[9];
    const float* to_kv_w   = (const float*)d_in[10];
    const float* to_out_w  = (const float*)d_in[11];
    const float* ff_g      = (const float*)d_in[12];
    const float* ff_tw     = (const float*)d_in[13];
    const float* ff_tb     = (const float*)d_in[14];
    const float* ff_in_w   = (const float*)d_in[15];
    const float* ff_in_b   = (const float*)d_in[16];
    const float* ff_out_w  = (const float*)d_in[17];
    const float* ff_out_b  = (const float*)d_in[18];

    float *tact, *scsh, *xn, *q, *kv, *sim, *ao, *hb;
    cudaGetSymbolAddress((void**)&tact, g_tact);
    cudaGetSymbolAddress((void**)&scsh, g_scsh);
    cudaGetSymbolAddress((void**)&xn, g_xn);
    cudaGetSymbolAddress((void**)&q, g_q);
    cudaGetSymbolAddress((void**)&kv, g_kv);
    cudaGetSymbolAddress((void**)&sim, g_sim);
    cudaGetSymbolAddress((void**)&ao, g_ao);
    cudaGetSymbolAddress((void**)&hb, g_hb);

    float* x = (float*)d_out;
    const int M = BB * NN;

    init_x_k<<<(BB * NN * DIMC + 255) / 256, 256>>>(x_in, seq_mask, x);
    silu_time_k<<<(BB * TCDD + 255) / 256, 256>>>(time_in, tact);

    for (int d = 0; d < DEPTHL; d++) {
        // --- attention block ---
        time_gemm_k<<<dim3((2 * DIMC + 255) / 256, BB), 256>>>(
            tact, attn_tw + (size_t)d * TCDD * 2 * DIMC, attn_tb + (size_t)d * 2 * DIMC,
            scsh, TCDD, 2 * DIMC);
        ln_mod_k<<<M, 256>>>(x, attn_g + d * DIMC, scsh, seq_mask, xn, 1);
        tgemm_k<<<dim3(HIDD / 128, M / 128), 256>>>(
            xn, to_q_w + (size_t)d * DIMC * HIDD, q, M, HIDD, DIMC,
            nullptr, nullptr, nullptr, nullptr, SCALEQ, 0);
        tgemm_k<<<dim3(2 * HIDD / 128, M / 128), 256>>>(
            x, to_kv_w + (size_t)d * DIMC * 2 * HIDD, kv, M, 2 * HIDD, DIMC,
            nullptr, nullptr, nullptr, nullptr, 1.f, 0);
        qk_mma_k<<<dim3(NN / 128, NN / 128, BB * HEADS), 256>>>(
            q, kv, res_idx, seq_mask, relpos_w, relpos_b, sim);
        softmax_k<<<BB * HEADS * NN, 256>>>(sim);
        av_mma_k<<<dim3(NN / 128, BB * HEADS), 256>>>(sim, kv, ao);
        tgemm_k<<<dim3(DIMC / 128, M / 128), 256>>>(
            ao, to_out_w + (size_t)d * HIDD * DIMC, x, M, DIMC, HIDD,
            nullptr, x, seq_mask, nullptr, 1.f, 2);

        // --- feed-forward block ---
        time_gemm_k<<<dim3((2 * INNERC + 255) / 256, BB), 256>>>(
            tact, ff_tw + (size_t)d * TCDD * 2 * INNERC, ff_tb + (size_t)d * 2 * INNERC,
            scsh, TCDD, 2 * INNERC);
        ln_mod_k<<<M, 256>>>(x, ff_g + d * DIMC, nullptr, nullptr, xn, 0);
        tgemm_k<<<dim3(INNERC / 128, M / 128), 256>>>(
            xn, ff_in_w + (size_t)d * DIMC * INNERC, hb, M, INNERC, DIMC,
            ff_in_b + (size_t)d * INNERC, nullptr, nullptr, scsh, 1.f, 1);
        tgemm_k<<<dim3(DIMC / 128, M / 128), 256>>>(
            hb, ff_out_w + (size_t)d * INNERC * DIMC, x, M, DIMC, INNERC,
            ff_out_b + (size_t)d * DIMC, x, seq_mask, nullptr, 1.f, 3);
    }
}

// round 3
// speedup vs baseline: 3.7960x; 1.6829x over previous
#include <cuda_runtime.h>
#include <math.h>
#include <stdint.h>

#define BB     4
#define NN     1024
#define DIMC   512
#define DEPTHL 4
#define HEADS  8
#define DH     64
#define TCDD   512
#define HIDD   512
#define INNERC 2048
#define MAXREL 32
#define SCALEQ 0.125f
#define LNEPS  1e-5f

// ---------------- scratch ----------------------------------------------------
__device__ float g_tact[BB * TCDD];
__device__ float g_scsh[BB * 2 * INNERC];
__device__ float g_xn[BB * NN * DIMC];
__device__ float g_q[BB * NN * HIDD];
__device__ float g_kv[BB * NN * 2 * HIDD];
__device__ float g_ao[BB * NN * HIDD];
__device__ float g_hb[BB * NN * INNERC];

// ---------------- helpers ----------------------------------------------------
#define MMA_TF32(c, a0, a1, a2, a3, b0, b1)                                     \
    asm volatile(                                                               \
        "mma.sync.aligned.m16n8k8.row.col.f32.tf32.tf32.f32 "                   \
        "{%0,%1,%2,%3},{%4,%5,%6,%7},{%8,%9},{%0,%1,%2,%3};"                    \
        : "+f"(c[0]), "+f"(c[1]), "+f"(c[2]), "+f"(c[3])                        \
        : "r"(a0), "r"(a1), "r"(a2), "r"(a3), "r"(b0), "r"(b1))

#define CPA16(dst, src)                                                         \
    asm volatile("cp.async.cg.shared.global [%0], [%1], 16;" ::"r"(dst), "l"(src))
#define CP_COMMIT() asm volatile("cp.async.commit_group;")
#define CP_WAIT(n)  asm volatile("cp.async.wait_group %0;" ::"n"(n))

__device__ __forceinline__ uint32_t smem_u32(const void* p) {
    return (uint32_t)__cvta_generic_to_shared(p);
}

// ---------------- small elementwise kernels ---------------------------------
__global__ void silu_time_k(const float* __restrict__ tm, float* __restrict__ out) {
    int i = blockIdx.x * 256 + threadIdx.x;
    if (i < BB * TCDD) {
        float v = tm[i];
        out[i] = v / (1.f + __expf(-v));
    }
}

__global__ void init_x_k(const float* __restrict__ xin, const float* __restrict__ mask,
                         float* __restrict__ x) {
    int i = blockIdx.x * 256 + threadIdx.x;
    if (i < BB * NN * DIMC) x[i] = xin[i] * mask[i / DIMC];
}

__global__ void time_gemm_k(const float* __restrict__ tact, const float* __restrict__ W,
                            const float* __restrict__ bias, float* __restrict__ out,
                            int K, int Ncols) {
    int n = blockIdx.x * 256 + threadIdx.x;
    int b = blockIdx.y;
    if (n >= Ncols) return;
    const float* t = tact + b * K;
    float acc = bias[n];
    for (int k = 0; k < K; k++) acc += t[k] * W[(size_t)k * Ncols + n];
    out[(size_t)b * Ncols + n] = acc;
}

// Warp-per-row LayerNorm (+AdaLN mod, +row mask)
__global__ __launch_bounds__(256)
void ln_mod_k(const float* __restrict__ x, const float* __restrict__ g,
              const float* __restrict__ scsh, const float* __restrict__ mask,
              float* __restrict__ out, int useMod) {
    int warp = threadIdx.x >> 5, lane = threadIdx.x & 31;
    int row = blockIdx.x * 8 + warp;
    const float* xr = x + (size_t)row * DIMC;
    float4 v[4];
    float s = 0.f, sq = 0.f;
#pragma unroll
    for (int i = 0; i < 4; i++) {
        v[i] = *(const float4*)(xr + i * 128 + lane * 4);
        s += v[i].x + v[i].y + v[i].z + v[i].w;
        sq += v[i].x * v[i].x + v[i].y * v[i].y + v[i].z * v[i].z + v[i].w * v[i].w;
    }
#pragma unroll
    for (int off = 16; off > 0; off >>= 1) {
        s += __shfl_xor_sync(0xffffffffu, s, off);
        sq += __shfl_xor_sync(0xffffffffu, sq, off);
    }
    float m = s * (1.f / DIMC);
    float rstd = rsqrtf(sq * (1.f / DIMC) - m * m + LNEPS);
    int b = row / NN;
    float mk = mask ? mask[row] : 1.f;
#pragma unroll
    for (int i = 0; i < 4; i++) {
        int c = i * 128 + lane * 4;
        float4 gg = *(const float4*)(g + c);
        float4 o;
        o.x = (v[i].x - m) * rstd * gg.x;
        o.y = (v[i].y - m) * rstd * gg.y;
        o.z = (v[i].z - m) * rstd * gg.z;
        o.w = (v[i].w - m) * rstd * gg.w;
        if (useMod) {
            const float* scp = scsh + b * 2 * DIMC + c;
            const float* shp = scp + DIMC;
            float4 sc = *(const float4*)scp, sh = *(const float4*)shp;
            o.x = o.x * (sc.x + 1.f) + sh.x;
            o.y = o.y * (sc.y + 1.f) + sh.y;
            o.z = o.z * (sc.z + 1.f) + sh.z;
            o.w = o.w * (sc.w + 1.f) + sh.w;
        }
        o.x *= mk; o.y *= mk; o.z *= mk; o.w *= mk;
        *(float4*)(out + (size_t)row * DIMC + c) = o;
    }
}

// ---------------- cp.async double-buffered tf32 GEMM -------------------------
// A stored [m][k] (stride 36), B stored [k][n] (stride 136). k-tile = 32.
#define ATILE 4608   // 128*36 floats
#define BTILE 4352   // 32*136 floats
#define TGEMM_SMEM ((2 * ATILE + 2 * BTILE) * 4)

__global__ __launch_bounds__(256, 2)
void tgemm_k(const float* __restrict__ A, const float* __restrict__ Bm,
             float* __restrict__ C, int M, int Ncols, int K,
             const float* __restrict__ bias, const float* __restrict__ residual,
             const float* __restrict__ rowmask, const float* __restrict__ mod,
             float alpha, int mode) {
    extern __shared__ float sm[];
    float* As = sm;
    float* Bs = sm + 2 * ATILE;
    uint32_t asB = smem_u32(As), bsB = smem_u32(Bs);
    int t = threadIdx.x;
    int lane = t & 31, warp = t >> 5;
    int gid = lane >> 2, tig = lane & 3;
    int wr = warp >> 1, wc = warp & 1;
    int rowBase = blockIdx.y * 128, colBase = blockIdx.x * 128;

    const float* gA = A + (size_t)rowBase * K;
    const float* gB = Bm + colBase;

    float acc[2][8][4];
#pragma unroll
    for (int i = 0; i < 2; i++)
#pragma unroll
        for (int j = 0; j < 8; j++)
#pragma unroll
            for (int c = 0; c < 4; c++) acc[i][j][c] = 0.f;

    int ntiles = K >> 5;

#define ISSUE_TILE(kt, st)                                                       \
    {                                                                            \
        int kk0 = (kt) << 5;                                                     \
        _Pragma("unroll") for (int l = 0; l < 4; l++) {                          \
            int idx = t + 256 * l;                                              \
            int mm = idx >> 3, ck = idx & 7;                                    \
            CPA16(asB + ((st)*ATILE + mm * 36 + ck * 4) * 4,                    \
                  gA + (size_t)mm * K + kk0 + ck * 4);                          \
        }                                                                        \
        _Pragma("unroll") for (int l = 0; l < 4; l++) {                          \
            int idx = t + 256 * l;                                              \
            int kk = idx >> 5, nc = idx & 31;                                   \
            CPA16(bsB + ((st)*BTILE + kk * 136 + nc * 4) * 4,                   \
                  gB + (size_t)(kk0 + kk) * Ncols + nc * 4);                    \
        }                                                                        \
        CP_COMMIT();                                                             \
    }

    ISSUE_TILE(0, 0);
    for (int it = 0; it < ntiles; it++) {
        int st = it & 1;
        if (it + 1 < ntiles) {
            ISSUE_TILE(it + 1, st ^ 1);
            CP_WAIT(1);
        } else {
            CP_WAIT(0);
        }
        __syncthreads();
        const float* Asb = As + st * ATILE;
        const float* Bsb = Bs + st * BTILE;
#pragma unroll
        for (int ks = 0; ks < 32; ks += 8) {
            uint32_t a[2][4];
#pragma unroll
            for (int mt = 0; mt < 2; mt++) {
                int m0 = wr * 32 + mt * 16;
                a[mt][0] = __float_as_uint(Asb[(m0 + gid) * 36 + ks + tig]);
                a[mt][1] = __float_as_uint(Asb[(m0 + gid + 8) * 36 + ks + tig]);
                a[mt][2] = __float_as_uint(Asb[(m0 + gid) * 36 + ks + tig + 4]);
                a[mt][3] = __float_as_uint(Asb[(m0 + gid + 8) * 36 + ks + tig + 4]);
            }
            uint32_t b[8][2];
#pragma unroll
            for (int nt = 0; nt < 8; nt++) {
                int n0 = wc * 64 + nt * 8;
                b[nt][0] = __float_as_uint(Bsb[(ks + tig) * 136 + n0 + gid]);
                b[nt][1] = __float_as_uint(Bsb[(ks + tig + 4) * 136 + n0 + gid]);
            }
#pragma unroll
            for (int mt = 0; mt < 2; mt++)
#pragma unroll
                for (int nt = 0; nt < 8; nt++)
                    MMA_TF32(acc[mt][nt], a[mt][0], a[mt][1], a[mt][2], a[mt][3],
                             b[nt][0], b[nt][1]);
        }
        __syncthreads();
    }
#undef ISSUE_TILE

#pragma unroll
    for (int mt = 0; mt < 2; mt++)
#pragma unroll
        for (int half = 0; half < 2; half++) {
            int i = rowBase + wr * 32 + mt * 16 + gid + half * 8;
            int b = i / NN;
            float rm = (mode >= 2) ? rowmask[i] : 1.f;
#pragma unroll
            for (int nt = 0; nt < 8; nt++) {
                int j = colBase + wc * 64 + nt * 8 + tig * 2;
                size_t off = (size_t)i * Ncols + j;
                float v0 = acc[mt][nt][half * 2 + 0] * alpha;
                float v1 = acc[mt][nt][half * 2 + 1] * alpha;
                if (mode == 0) {
                    if (bias) { v0 += bias[j]; v1 += bias[j + 1]; }
                } else if (mode == 1) {
                    v0 += bias[j];
                    v1 += bias[j + 1];
                    v0 = v0 / (1.f + __expf(-v0));
                    v1 = v1 / (1.f + __expf(-v1));
                    float sc0 = mod[b * 2 * Ncols + j], sc1 = mod[b * 2 * Ncols + j + 1];
                    float sh0 = mod[b * 2 * Ncols + Ncols + j];
                    float sh1 = mod[b * 2 * Ncols + Ncols + j + 1];
                    v0 = v0 * (sc0 + 1.f) + sh0;
                    v1 = v1 * (sc1 + 1.f) + sh1;
                } else if (mode == 2) {
                    float2 r = *(const float2*)(residual + off);
                    v0 = r.x + v0 * rm;
                    v1 = r.y + v1 * rm;
                } else {
                    float2 r = *(const float2*)(residual + off);
                    v0 = (r.x + v0 + bias[j]) * rm;
                    v1 = (r.y + v1 + bias[j + 1]) * rm;
                }
                *(float2*)(C + off) = make_float2(v0, v1);
            }
        }
}

// ---------------- flash attention --------------------------------------------
// BM=128 (8 warps x 16 rows), BN=64 per j-step. Online softmax, no sim buffer.
#define QS_FLOATS (128 * 68)
#define KS_FLOATS (64 * 68)
#define VS_FLOATS (64 * 72)
#define FLASH_SMEM ((QS_FLOATS + KS_FLOATS + VS_FLOATS + 65 + 64 + 64 + 3) * 4)

__global__ __launch_bounds__(256, 2)
void flash_k(const float* __restrict__ q, const float* __restrict__ kv,
             const int* __restrict__ ri, const float* __restrict__ mask,
             const float* __restrict__ rw, const float* __restrict__ rb,
             float* __restrict__ ao) {
    extern __shared__ float sm[];
    float* Qs = sm;
    float* Ks = Qs + QS_FLOATS;
    float* Vs = Ks + KS_FLOATS;
    float* rws = Vs + VS_FLOATS;   // 65
    float* mjs = rws + 65;         // 64
    int* rji = (int*)(mjs + 64);   // 64

    int b = blockIdx.y / HEADS, h = blockIdx.y % HEADS;
    int i0 = blockIdx.x * 128;
    int t = threadIdx.x;
    int lane = t & 31, warp = t >> 5;
    int gid = lane >> 2, tig = lane & 3;

    // load Q tile (raw fp32; HW truncates to tf32)
#pragma unroll
    for (int l = 0; l < 8; l++) {
        int idx = t + 256 * l;
        int r = idx >> 4, dv = idx & 15;
        *(float4*)&Qs[r * 68 + dv * 4] =
            *(const float4*)(q + (size_t)(b * NN + i0 + r) * HIDD + h * DH + dv * 4);
    }
    if (t < 65) rws[t] = rw[t * HEADS + h] + rb[h];
    __syncthreads();

    int row0 = i0 + warp * 16 + gid;
    int row1 = row0 + 8;
    int ri0 = ri[b * NN + row0], ri1 = ri[b * NN + row1];
    float mi0 = mask[b * NN + row0], mi1 = mask[b * NN + row1];

    float O[8][4];
#pragma unroll
    for (int nt = 0; nt < 8; nt++)
#pragma unroll
        for (int c = 0; c < 4; c++) O[nt][c] = 0.f;
    float m0 = -1e30f, m1 = -1e30f, l0 = 0.f, l1 = 0.f;

    for (int j0 = 0; j0 < NN; j0 += 64) {
        // load K/V tiles + per-j metadata
#pragma unroll
        for (int l = 0; l < 4; l++) {
            int idx = t + 256 * l;
            int r = idx >> 4, dv = idx & 15;
            const float* base = kv + (size_t)(b * NN + j0 + r) * 2 * HIDD + h * DH;
            *(float4*)&Ks[r * 68 + dv * 4] = *(const float4*)(base + dv * 4);
            *(float4*)&Vs[r * 72 + dv * 4] = *(const float4*)(base + HIDD + dv * 4);
        }
        if (t < 64) {
            rji[t] = ri[b * NN + j0 + t];
            mjs[t] = mask[b * NN + j0 + t];
        }
        __syncthreads();

        // S = Q K^T  (warp: 16 x 64)
        float S[8][4];
#pragma unroll
        for (int nt = 0; nt < 8; nt++)
#pragma unroll
            for (int c = 0; c < 4; c++) S[nt][c] = 0.f;
#pragma unroll
        for (int ks = 0; ks < 64; ks += 8) {
            uint32_t a0 = __float_as_uint(Qs[(warp * 16 + gid) * 68 + ks + tig]);
            uint32_t a1 = __float_as_uint(Qs[(warp * 16 + gid + 8) * 68 + ks + tig]);
            uint32_t a2 = __float_as_uint(Qs[(warp * 16 + gid) * 68 + ks + tig + 4]);
            uint32_t a3 = __float_as_uint(Qs[(warp * 16 + gid + 8) * 68 + ks + tig + 4]);
#pragma unroll
            for (int nt = 0; nt < 8; nt++) {
                uint32_t b0 = __float_as_uint(Ks[(nt * 8 + gid) * 68 + ks + tig]);
                uint32_t b1 = __float_as_uint(Ks[(nt * 8 + gid) * 68 + ks + tig + 4]);
                MMA_TF32(S[nt], a0, a1, a2, a3, b0, b1);
            }
        }

        // bias + mask
#pragma unroll
        for (int nt = 0; nt < 8; nt++) {
            int jl0 = nt * 8 + 2 * tig, jl1 = jl0 + 1;
            int rj0 = rji[jl0], rj1 = rji[jl1];
            float mj0 = mjs[jl0], mj1 = mjs[jl1];
            int d00 = min(max(ri0 - rj0, -MAXREL), MAXREL) + MAXREL;
            int d01 = min(max(ri0 - rj1, -MAXREL), MAXREL) + MAXREL;
            int d10 = min(max(ri1 - rj0, -MAXREL), MAXREL) + MAXREL;
            int d11 = min(max(ri1 - rj1, -MAXREL), MAXREL) + MAXREL;
            S[nt][0] += rws[d00] - (1.f - mi0 * mj0) * 1e6f;
            S[nt][1] += rws[d01] - (1.f - mi0 * mj1) * 1e6f;
            S[nt][2] += rws[d10] - (1.f - mi1 * mj0) * 1e6f;
            S[nt][3] += rws[d11] - (1.f - mi1 * mj1) * 1e6f;
        }

        // row maxes (quad reduce)
        float mx0 = -1e30f, mx1 = -1e30f;
#pragma unroll
        for (int nt = 0; nt < 8; nt++) {
            mx0 = fmaxf(mx0, fmaxf(S[nt][0], S[nt][1]));
            mx1 = fmaxf(mx1, fmaxf(S[nt][2], S[nt][3]));
        }
        mx0 = fmaxf(mx0, __shfl_xor_sync(0xffffffffu, mx0, 1));
        mx0 = fmaxf(mx0, __shfl_xor_sync(0xffffffffu, mx0, 2));
        mx1 = fmaxf(mx1, __shfl_xor_sync(0xffffffffu, mx1, 1));
        mx1 = fmaxf(mx1, __shfl_xor_sync(0xffffffffu, mx1, 2));
        float m0n = fmaxf(m0, mx0), m1n = fmaxf(m1, mx1);
        float sc0 = __expf(m0 - m0n), sc1 = __expf(m1 - m1n);
        m0 = m0n; m1 = m1n;

        // P = exp(S - m), row sums
        float sum0 = 0.f, sum1 = 0.f;
#pragma unroll
        for (int nt = 0; nt < 8; nt++) {
            S[nt][0] = __expf(S[nt][0] - m0n);
            S[nt][1] = __expf(S[nt][1] - m0n);
            S[nt][2] = __expf(S[nt][2] - m1n);
            S[nt][3] = __expf(S[nt][3] - m1n);
            sum0 += S[nt][0] + S[nt][1];
            sum1 += S[nt][2] + S[nt][3];
        }
        sum0 += __shfl_xor_sync(0xffffffffu, sum0, 1);
        sum0 += __shfl_xor_sync(0xffffffffu, sum0, 2);
        sum1 += __shfl_xor_sync(0xffffffffu, sum1, 1);
        sum1 += __shfl_xor_sync(0xffffffffu, sum1, 2);
        l0 = l0 * sc0 + sum0;
        l1 = l1 * sc1 + sum1;

        // rescale O
#pragma unroll
        for (int nt = 0; nt < 8; nt++) {
            O[nt][0] *= sc0; O[nt][1] *= sc0;
            O[nt][2] *= sc1; O[nt][3] *= sc1;
        }

        // O += P @ V : convert P C-frags -> A-frags via quad shuffles
        int src1 = (lane & ~3) | (tig >> 1);
        int src2 = src1 + 2;
#pragma unroll
        for (int kt = 0; kt < 8; kt++) {
            float s0a = __shfl_sync(0xffffffffu, S[kt][0], src1);
            float s0b = __shfl_sync(0xffffffffu, S[kt][1], src1);
            float s2a = __shfl_sync(0xffffffffu, S[kt][0], src2);
            float s2b = __shfl_sync(0xffffffffu, S[kt][1], src2);
            float s1a = __shfl_sync(0xffffffffu, S[kt][2], src1);
            float s1b = __shfl_sync(0xffffffffu, S[kt][3], src1);
            float s3a = __shfl_sync(0xffffffffu, S[kt][2], src2);
            float s3b = __shfl_sync(0xffffffffu, S[kt][3], src2);
            uint32_t a0 = __float_as_uint((tig & 1) ? s0b : s0a);
            uint32_t a2 = __float_as_uint((tig & 1) ? s2b : s2a);
            uint32_t a1 = __float_as_uint((tig & 1) ? s1b : s1a);
            uint32_t a3 = __float_as_uint((tig & 1) ? s3b : s3a);
#pragma unroll
            for (int nt = 0; nt < 8; nt++) {
                uint32_t b0 = __float_as_uint(Vs[(kt * 8 + tig) * 72 + nt * 8 + gid]);
                uint32_t b1 = __float_as_uint(Vs[(kt * 8 + tig + 4) * 72 + nt * 8 + gid]);
                MMA_TF32(O[nt], a0, a1, a2, a3, b0, b1);
            }
        }
        __syncthreads();
    }

    float inv0 = 1.f / l0, inv1 = 1.f / l1;
#pragma unroll
    for (int nt = 0; nt < 8; nt++) {
        int dd = nt * 8 + tig * 2;
        *(float2*)(ao + (size_t)(b * NN + row0) * HIDD + h * DH + dd) =
            make_float2(O[nt][0] * inv0, O[nt][1] * inv0);
        *(float2*)(ao + (size_t)(b * NN + row1) * HIDD + h * DH + dd) =
            make_float2(O[nt][2] * inv1, O[nt][3] * inv1);
    }
}

// ---------------- launch -----------------------------------------------------
extern "C" void kernel_launch(void* const* d_in, const int* in_sizes, int n_in,
                              void* d_out, int out_size) {
    const float* x_in      = (const float*)d_in[0];
    const float* time_in   = (const float*)d_in[1];
    const float* seq_mask  = (const float*)d_in[2];
    const int*   res_idx   = (const int*)d_in[3];
    const float* relpos_w  = (const float*)d_in[4];
    const float* relpos_b  = (const float*)d_in[5];
    const float* attn_g    = (const float*)d_in[6];
    const float* attn_tw   = (const float*)d_in[7];
    const float* attn_tb   = (const float*)d_in[8];
    const float* to_q_w    = (const float*)d_in[9];
    const float* to_kv_w   = (const float*)d_in[10];
    const float* to_out_w  = (const float*)d_in[11];
    const float* ff_g      = (const float*)d_in[12];
    const float* ff_tw     = (const float*)d_in[13];
    const float* ff_tb     = (const float*)d_in[14];
    const float* ff_in_w   = (const float*)d_in[15];
    const float* ff_in_b   = (const float*)d_in[16];
    const float* ff_out_w  = (const float*)d_in[17];
    const float* ff_out_b  = (const float*)d_in[18];

    float *tact, *scsh, *xn, *q, *kv, *ao, *hb;
    cudaGetSymbolAddress((void**)&tact, g_tact);
    cudaGetSymbolAddress((void**)&scsh, g_scsh);
    cudaGetSymbolAddress((void**)&xn, g_xn);
    cudaGetSymbolAddress((void**)&q, g_q);
    cudaGetSymbolAddress((void**)&kv, g_kv);
    cudaGetSymbolAddress((void**)&ao, g_ao);
    cudaGetSymbolAddress((void**)&hb, g_hb);

    cudaFuncSetAttribute(tgemm_k, cudaFuncAttributeMaxDynamicSharedMemorySize,
                         TGEMM_SMEM);
    cudaFuncSetAttribute(flash_k, cudaFuncAttributeMaxDynamicSharedMemorySize,
                         FLASH_SMEM);

    float* x = (float*)d_out;
    const int M = BB * NN;

    init_x_k<<<(BB * NN * DIMC + 255) / 256, 256>>>(x_in, seq_mask, x);
    silu_time_k<<<(BB * TCDD + 255) / 256, 256>>>(time_in, tact);

    for (int d = 0; d < DEPTHL; d++) {
        // --- attention block ---
        time_gemm_k<<<dim3((2 * DIMC + 255) / 256, BB), 256>>>(
            tact, attn_tw + (size_t)d * TCDD * 2 * DIMC, attn_tb + (size_t)d * 2 * DIMC,
            scsh, TCDD, 2 * DIMC);
        ln_mod_k<<<M / 8, 256>>>(x, attn_g + d * DIMC, scsh, seq_mask, xn, 1);
        tgemm_k<<<dim3(HIDD / 128, M / 128), 256, TGEMM_SMEM>>>(
            xn, to_q_w + (size_t)d * DIMC * HIDD, q, M, HIDD, DIMC,
            nullptr, nullptr, nullptr, nullptr, SCALEQ, 0);
        tgemm_k<<<dim3(2 * HIDD / 128, M / 128), 256, TGEMM_SMEM>>>(
            x, to_kv_w + (size_t)d * DIMC * 2 * HIDD, kv, M, 2 * HIDD, DIMC,
            nullptr, nullptr, nullptr, nullptr, 1.f, 0);
        flash_k<<<dim3(NN / 128, BB * HEADS), 256, FLASH_SMEM>>>(
            q, kv, res_idx, seq_mask, relpos_w, relpos_b, ao);
        tgemm_k<<<dim3(DIMC / 128, M / 128), 256, TGEMM_SMEM>>>(
            ao, to_out_w + (size_t)d * HIDD * DIMC, x, M, DIMC, HIDD,
            nullptr, x, seq_mask, nullptr, 1.f, 2);

        // --- feed-forward block ---
        time_gemm_k<<<dim3((2 * INNERC + 255) / 256, BB), 256>>>(
            tact, ff_tw + (size_t)d * TCDD * 2 * INNERC, ff_tb + (size_t)d * 2 * INNERC,
            scsh, TCDD, 2 * INNERC);
        ln_mod_k<<<M / 8, 256>>>(x, ff_g + d * DIMC, nullptr, nullptr, xn, 0);
        tgemm_k<<<dim3(INNERC / 128, M / 128), 256, TGEMM_SMEM>>>(
            xn, ff_in_w + (size_t)d * DIMC * INNERC, hb, M, INNERC, DIMC,
            ff_in_b + (size_t)d * INNERC, nullptr, nullptr, scsh, 1.f, 1);
        tgemm_k<<<dim3(DIMC / 128, M / 128), 256, TGEMM_SMEM>>>(
            hb, ff_out_w + (size_t)d * INNERC * DIMC, x, M, DIMC, INNERC,
            ff_out_b + (size_t)d * DIMC, x, seq_mask, nullptr, 1.f, 3);
    }
}